// round 17
// baseline (speedup 1.0000x reference)
#include <cuda_runtime.h>
#include <cuda_bf16.h>
#include <stdint.h>

// LengthRegulator: B=32, S=1024, E=256
//   cum = cumsum(duration, axis=1); mel_len = cum[:, -1]; max_mel = max(mel_len)
//   out[b, t, :] = x[b, idx(b,t), :]  (searchsorted-right), tail rows zero,
//   mask[b,t] = (t >= mel_len[b]).
// Output buffer: [ out (B*max_mel*E f32) | mask (B*max_mel f32) ] if has_mask.
//
// R16: run-length load dedup. Scatter also records run lengths; each warp
// walks its 8-row range run-by-run, loading each distinct source row ONCE
// (2x LDG.128, double-buffered prefetch of the next run) and storing it to
// r consecutive output rows. Cuts load-side L1 wavefronts ~2.7x; store
// traffic (compulsory) unchanged. Discriminates L1/LSU-bound vs DRAM-bound.

#define BB 32
#define SS 1024
#define EE 256

#define NTHR  512
#define WPB   16                 // warps per block
#define RPW   8                  // output rows per warp
#define WIN   (WPB * RPW)        // 128 output rows per block
#define EPT   2                  // duration elements per thread (1024/512)

__global__ __launch_bounds__(NTHR)
void lr_fused_kernel(const float* __restrict__ x,
                     const void* __restrict__ dur_raw,
                     float* __restrict__ out,
                     int max_mel, int has_mask) {
    __shared__ int s_idx[WIN];      // source row per window position
    __shared__ int s_run[WIN];      // run length (clipped to window) from t
    __shared__ int s_warpsum[WPB];
    __shared__ int s_is64;

    const int b    = blockIdx.y;
    const int W0   = blockIdx.x * WIN;
    const int tid  = threadIdx.x;
    const int lane = tid & 31;
    const int wid  = tid >> 5;

    // ---- dtype detect: int64 LE => odd 32-bit words are zero high-halves.
    if (wid == 0) {
        const unsigned* w = (const unsigned*)dur_raw;
        unsigned acc = 0;
        #pragma unroll
        for (int k = 0; k < 4; ++k) acc |= w[2 * (lane * 4 + k) + 1];
        unsigned any = __any_sync(0xffffffffu, acc != 0u);
        if (lane == 0) s_is64 = any ? 0 : 1;
    }
    __syncthreads();

    // ---- load 2 durations / thread
    int d[EPT];
    if (s_is64) {
        const long long* p = (const long long*)dur_raw + (size_t)b * SS + tid * EPT;
        #pragma unroll
        for (int e = 0; e < EPT; ++e) d[e] = (int)p[e];
    } else {
        const int* p = (const int*)dur_raw + (size_t)b * SS + tid * EPT;
        #pragma unroll
        for (int e = 0; e < EPT; ++e) d[e] = p[e];
    }

    // ---- block inclusive scan of 1024 durations
    int pfx[EPT];
    pfx[0] = d[0];
    #pragma unroll
    for (int e = 1; e < EPT; ++e) pfx[e] = pfx[e - 1] + d[e];
    const int tot = pfx[EPT - 1];

    int sv = tot;
    #pragma unroll
    for (int o = 1; o < 32; o <<= 1) {
        int n = __shfl_up_sync(0xffffffffu, sv, o);
        if (lane >= o) sv += n;
    }
    if (lane == 31) s_warpsum[wid] = sv;
    __syncthreads();
    if (wid == 0) {
        int ws = (lane < WPB) ? s_warpsum[lane] : 0;
        #pragma unroll
        for (int o = 1; o < WPB; o <<= 1) {
            int n = __shfl_up_sync(0xffffffffu, ws, o);
            if (lane >= o) ws += n;
        }
        if (lane < WPB) s_warpsum[lane] = ws;
    }
    __syncthreads();

    const int thr_base = (sv - tot) + (wid > 0 ? s_warpsum[wid - 1] : 0);
    const int L = s_warpsum[WPB - 1];            // mel_len[b]

    // ---- scatter: source elem EPT*tid+e covers [thr_base+pfx[e-1], +pfx[e]).
    // Record both source index and remaining run length at each position.
    const int W1 = W0 + WIN;
    {
        int exc = thr_base;
        #pragma unroll
        for (int e = 0; e < EPT; ++e) {
            const int inc = thr_base + pfx[e];
            int lo = exc > W0 ? exc : W0;
            int hi = inc < W1 ? inc : W1;
            for (int t = lo; t < hi; ++t) {
                s_idx[t - W0] = tid * EPT + e;
                s_run[t - W0] = hi - t;
            }
            exc = inc;
        }
    }
    __syncthreads();

    // ---- mask for this window (coalesced)
    if (has_mask && tid < WIN) {
        const int t = W0 + tid;
        if (t < max_mel)
            out[(size_t)BB * max_mel * EE + (size_t)b * max_mel + t] =
                (t >= L) ? 1.0f : 0.0f;
    }

    // ---- expand: per warp, walk runs. One row load per distinct source,
    // next run prefetched while current stores. Uniform control flow.
    const float* __restrict__ xb = x + (size_t)b * SS * EE;
    const float4 z = make_float4(0.f, 0.f, 0.f, 0.f);

    int t = W0 + wid * RPW;
    const int we_ = t + RPW;
    const int we  = we_ < max_mel ? we_ : max_mel;   // store end
    const int le  = we < L ? we : L;                 // live end

    if (t < le) {
        int s = s_idx[t - W0];
        int r = s_run[t - W0];
        if (r > le - t) r = le - t;
        const float4* xr = (const float4*)(xb + (size_t)s * EE);
        float4 a0 = __ldg(&xr[lane]);
        float4 a1 = __ldg(&xr[lane + 32]);

        while (true) {
            const int tn = t + r;
            const bool more = tn < le;
            int r2 = 0;
            float4 b0, b1;
            if (more) {                              // prefetch next run's row
                const int s2 = s_idx[tn - W0];
                r2 = s_run[tn - W0];
                if (r2 > le - tn) r2 = le - tn;
                const float4* xr2 = (const float4*)(xb + (size_t)s2 * EE);
                b0 = __ldg(&xr2[lane]);
                b1 = __ldg(&xr2[lane + 32]);
            }
            // store current run to r consecutive rows
            float4* ob = (float4*)(out + ((size_t)b * max_mel + t) * EE);
            for (int i = 0; i < r; ++i) {
                __stcs(&ob[i * (EE / 4) + lane],      a0);
                __stcs(&ob[i * (EE / 4) + lane + 32], a1);
            }
            if (!more) break;
            t = tn; r = r2; a0 = b0; a1 = b1;
        }
        t = le;
    }

    // zero tail rows [le, we)
    for (; t < we; ++t) {
        float4* ob = (float4*)(out + ((size_t)b * max_mel + t) * EE);
        __stcs(&ob[lane],      z);
        __stcs(&ob[lane + 32], z);
    }
}

// ---------------------------------------------------------------------------
extern "C" void kernel_launch(void* const* d_in, const int* in_sizes, int n_in,
                              void* d_out, int out_size) {
    (void)in_sizes; (void)n_in;
    const float* x   = (const float*)d_in[0];
    const void*  dur = d_in[1];
    float* out = (float*)d_out;

    // Derive max_mel / layout from out_size (fixed per run).
    int has_mask, max_mel;
    if (out_size % (BB * (EE + 1)) == 0) {
        has_mask = 1;
        max_mel  = out_size / (BB * (EE + 1));
    } else {
        has_mask = 0;
        max_mel  = out_size / (BB * EE);
    }

    dim3 grid((max_mel + WIN - 1) / WIN, BB);
    lr_fused_kernel<<<grid, NTHR>>>(x, dur, out, max_mel, has_mask);
}